// round 5
// baseline (speedup 1.0000x reference)
#include <cuda_runtime.h>
#include <cuda_bf16.h>
#include <cuda_fp16.h>
#include <cstdint>

#define N_NODES 100000
#define N_EDGES 1600000
#define D 128
#define SCAN_BS 512
#define NB ((N_NODES + SCAN_BS - 1) / SCAN_BS)   // 196
#define GEMM_TILE_M 128
#define GEMM_GRID ((N_NODES + GEMM_TILE_M - 1) / GEMM_TILE_M)   // 782
#define PITCH_B 272   // bytes per smem row: 128 bf16 = 256B + 16B pad (conflict-free ldmatrix)

// ---------------- scratch (__device__ globals; no allocation allowed) -------
__device__ float g_agg[N_NODES * D];     // dinv[c] * (sum dinv[r] x[r] + 2 dinv[c] x[c])
__device__ __half g_xh[N_NODES * D];     // fp16 copy of x for the gather
__device__ float g_dinv[N_NODES];
__device__ int   g_cnt[N_NODES];
__device__ int   g_cur[N_NODES];
__device__ int   g_rowptr[N_NODES];
__device__ int   g_src[N_EDGES];
__device__ int   g_bsum[NB];
__device__ int   g_bpre[NB];
// bf16 hi/lo weight images, layout [half][n:128][k:128] (B[n][k] = W[k_global][n])
__device__ __align__(16) unsigned char g_Bhi[65536];
__device__ __align__(16) unsigned char g_Blo[65536];

// ---------------- degree / CSR build ---------------------------------------
__global__ void k_zero() {
    int i = blockIdx.x * blockDim.x + threadIdx.x;
    if (i < N_NODES) { g_cnt[i] = 0; g_cur[i] = 0; }
}

__global__ void k_count(const int* __restrict__ col) {
    int e = blockIdx.x * blockDim.x + threadIdx.x;
    if (e < N_EDGES) atomicAdd(&g_cnt[col[e]], 1);
}

__global__ void k_prep(const float* __restrict__ x) {
    int i = blockIdx.x * blockDim.x + threadIdx.x;   // float4 index, N*32
    if (i >= N_NODES * 32) return;
    float4 v = ((const float4*)x)[i];
    __half2 a = __floats2half2_rn(v.x, v.y);
    __half2 b = __floats2half2_rn(v.z, v.w);
    uint2 u;
    u.x = *(uint32_t*)&a;
    u.y = *(uint32_t*)&b;
    ((uint2*)g_xh)[i] = u;
}

__global__ void k_blocksum() {
    __shared__ int s[SCAN_BS];
    int t = threadIdx.x;
    int i = blockIdx.x * SCAN_BS + t;
    s[t] = (i < N_NODES) ? g_cnt[i] : 0;
    __syncthreads();
    for (int off = SCAN_BS / 2; off > 0; off >>= 1) {
        if (t < off) s[t] += s[t + off];
        __syncthreads();
    }
    if (t == 0) g_bsum[blockIdx.x] = s[0];
}

__global__ void k_scanbsum() {
    __shared__ int s[256];
    int t = threadIdx.x;
    int v = (t < NB) ? g_bsum[t] : 0;
    s[t] = v;
    __syncthreads();
    for (int off = 1; off < 256; off <<= 1) {
        int u = (t >= off) ? s[t - off] : 0;
        __syncthreads();
        s[t] += u;
        __syncthreads();
    }
    if (t < NB) g_bpre[t] = s[t] - v;
}

__global__ void k_scanblock() {
    __shared__ int s[SCAN_BS];
    int t = threadIdx.x;
    int i = blockIdx.x * SCAN_BS + t;
    int v = (i < N_NODES) ? g_cnt[i] : 0;
    s[t] = v;
    __syncthreads();
    for (int off = 1; off < SCAN_BS; off <<= 1) {
        int u = (t >= off) ? s[t - off] : 0;
        __syncthreads();
        s[t] += u;
        __syncthreads();
    }
    if (i < N_NODES) {
        g_rowptr[i] = s[t] - v + g_bpre[blockIdx.x];
        g_dinv[i] = rsqrtf((float)(v + 2));
    }
}

__global__ void k_fill(const int* __restrict__ rowv, const int* __restrict__ colv) {
    int e = blockIdx.x * blockDim.x + threadIdx.x;
    if (e >= N_EDGES) return;
    int c = colv[e];
    int pos = g_rowptr[c] + atomicAdd(&g_cur[c], 1);
    g_src[pos] = rowv[e];
}

// ---------------- warp-per-node gather aggregation (fp16 gather) ------------
__global__ void k_agg(const float* __restrict__ x) {
    int w = (blockIdx.x * blockDim.x + threadIdx.x) >> 5;
    int lane = threadIdx.x & 31;
    if (w >= N_NODES) return;
    const uint2* xh2 = (const uint2*)g_xh;   // 32 uint2 per row (4 halves each)
    const float4* x4 = (const float4*)x;

    int start = g_rowptr[w];
    int cn = g_cnt[w];
    float dc = g_dinv[w];

    float ax = 0.f, ay = 0.f, az = 0.f, aw = 0.f;

    for (int base = 0; base < cn; base += 32) {
        int idx = 0;
        if (base + lane < cn) idx = g_src[start + base + lane];
        int m = min(32, cn - base);
        int j = 0;
        for (; j + 4 <= m; j += 4) {
            int s0 = __shfl_sync(0xffffffffu, idx, j);
            int s1 = __shfl_sync(0xffffffffu, idx, j + 1);
            int s2 = __shfl_sync(0xffffffffu, idx, j + 2);
            int s3 = __shfl_sync(0xffffffffu, idx, j + 3);
            float d0 = g_dinv[s0], d1 = g_dinv[s1], d2 = g_dinv[s2], d3 = g_dinv[s3];
            uint2 u0 = xh2[s0 * 32 + lane];
            uint2 u1 = xh2[s1 * 32 + lane];
            uint2 u2 = xh2[s2 * 32 + lane];
            uint2 u3 = xh2[s3 * 32 + lane];
            float2 a0 = __half22float2(*(__half2*)&u0.x), b0 = __half22float2(*(__half2*)&u0.y);
            float2 a1 = __half22float2(*(__half2*)&u1.x), b1 = __half22float2(*(__half2*)&u1.y);
            float2 a2 = __half22float2(*(__half2*)&u2.x), b2 = __half22float2(*(__half2*)&u2.y);
            float2 a3 = __half22float2(*(__half2*)&u3.x), b3 = __half22float2(*(__half2*)&u3.y);
            ax += d0 * a0.x + d1 * a1.x + d2 * a2.x + d3 * a3.x;
            ay += d0 * a0.y + d1 * a1.y + d2 * a2.y + d3 * a3.y;
            az += d0 * b0.x + d1 * b1.x + d2 * b2.x + d3 * b3.x;
            aw += d0 * b0.y + d1 * b1.y + d2 * b2.y + d3 * b3.y;
        }
        for (; j < m; j++) {
            int s0 = __shfl_sync(0xffffffffu, idx, j);
            float d0 = g_dinv[s0];
            uint2 u0 = xh2[s0 * 32 + lane];
            float2 a0 = __half22float2(*(__half2*)&u0.x), b0 = __half22float2(*(__half2*)&u0.y);
            ax += d0 * a0.x; ay += d0 * a0.y; az += d0 * b0.x; aw += d0 * b0.y;
        }
    }

    // self-loop term in full fp32, then prescale everything by dinv[w]
    float4 xv = x4[w * 32 + lane];
    float td = 2.f * dc;
    float4 r;
    r.x = dc * (ax + td * xv.x);
    r.y = dc * (ay + td * xv.y);
    r.z = dc * (az + td * xv.z);
    r.w = dc * (aw + td * xv.w);
    ((float4*)g_agg)[w * 32 + lane] = r;
}

// ---------------- weight pre-conversion (plain [half][n][k] layout) ---------
__global__ void k_wconv(const float* __restrict__ Wconv, const float* __restrict__ Wproj) {
    int t = blockIdx.x * blockDim.x + threadIdx.x;  // 16384 = 128 n * 128 k-pairs
    if (t >= 128 * 128) return;
    int n = t >> 7;
    int p = t & 127;
    int k0 = 2 * p, k1 = k0 + 1;
    float v0 = (k0 < D) ? Wconv[k0 * D + n] : Wproj[(k0 - D) * D + n];
    float v1 = (k1 < D) ? Wconv[k1 * D + n] : Wproj[(k1 - D) * D + n];
    __nv_bfloat16 h0 = __float2bfloat16_rn(v0);
    __nv_bfloat16 h1 = __float2bfloat16_rn(v1);
    __nv_bfloat16 l0 = __float2bfloat16_rn(v0 - __bfloat162float(h0));
    __nv_bfloat16 l1 = __float2bfloat16_rn(v1 - __bfloat162float(h1));
    uint32_t hp = (uint32_t)__bfloat16_as_ushort(h0) | ((uint32_t)__bfloat16_as_ushort(h1) << 16);
    uint32_t lp = (uint32_t)__bfloat16_as_ushort(l0) | ((uint32_t)__bfloat16_as_ushort(l1) << 16);
    int half = k0 >> 7;
    int klocal = k0 & 127;
    uint32_t off = ((uint32_t)half * 16384 + n * 128 + klocal) * 2;   // bytes
    *(uint32_t*)(g_Bhi + off) = hp;
    *(uint32_t*)(g_Blo + off) = lp;
}

// ---------------- mma.sync split-bf16 GEMM + fused epilogue -----------------
// smem byte offsets
#define SM_AHI 0
#define SM_ALO 34816
#define SM_BHI 69632
#define SM_BLO 104448
#define SM_MISC 139264
#define SM_TOTAL 140800
// misc: sB[128]f @ +0, sO[128]f @ +512, sRes[128]f @ +1024

__device__ __forceinline__ uint32_t s2u(const void* p) {
    uint32_t a;
    asm("{ .reg .u64 t; cvta.to.shared.u64 t, %1; cvt.u32.u64 %0, t; }" : "=r"(a) : "l"(p));
    return a;
}
__device__ __forceinline__ void ldsm4(uint32_t* r, uint32_t addr) {
    asm volatile("ldmatrix.sync.aligned.m8n8.x4.shared.b16 {%0,%1,%2,%3}, [%4];"
                 : "=r"(r[0]), "=r"(r[1]), "=r"(r[2]), "=r"(r[3]) : "r"(addr));
}
__device__ __forceinline__ void mma16816(float* c, const uint32_t* a, uint32_t b0, uint32_t b1) {
    asm volatile(
        "mma.sync.aligned.m16n8k16.row.col.f32.bf16.bf16.f32 "
        "{%0,%1,%2,%3}, {%4,%5,%6,%7}, {%8,%9}, {%0,%1,%2,%3};"
        : "+f"(c[0]), "+f"(c[1]), "+f"(c[2]), "+f"(c[3])
        : "r"(a[0]), "r"(a[1]), "r"(a[2]), "r"(a[3]), "r"(b0), "r"(b1));
}

__global__ __launch_bounds__(256, 1)
void k_gemm(const float* __restrict__ x,
            const float* __restrict__ bconv, const float* __restrict__ bproj,
            const float* __restrict__ Wout,  const float* __restrict__ bout,
            float* __restrict__ out) {
    extern __shared__ char sm[];
    uint32_t sb = s2u(sm);
    int tid = threadIdx.x;
    int wid = tid >> 5;
    int lane = tid & 31;
    int mBase = blockIdx.x * GEMM_TILE_M;

    float* sB = (float*)(sm + SM_MISC);
    float* sO = (float*)(sm + SM_MISC + 512);
    float* sRes = (float*)(sm + SM_MISC + 1024);

    if (tid < D) {
        sB[tid] = bconv[tid] + bproj[tid];
        sO[tid] = Wout[tid];
        sRes[tid] = 0.f;
    }

    int warp_m = wid >> 1;   // 0..3 -> rows 32*warp_m
    int warp_n = wid & 1;    // 0..1 -> cols 64*warp_n

    float acc[2][8][4];
#pragma unroll
    for (int mt = 0; mt < 2; mt++)
#pragma unroll
        for (int nt = 0; nt < 8; nt++)
#pragma unroll
            for (int j = 0; j < 4; j++) acc[mt][nt][j] = 0.f;

    const float4* agg4 = (const float4*)g_agg;
    const float4* x4 = (const float4*)x;
    int l8 = lane & 7;
    int sel = lane >> 3;

    for (int h = 0; h < 2; h++) {
        __syncthreads();   // previous-half smem fully consumed (also covers sB/sO init)

        // ---- convert A half into smem hi/lo, padded rows ----
#pragma unroll
        for (int p = 0; p < 16; p++) {
            int i = p * 256 + tid;      // 4096 float4 over [128 rows][32 q]
            int m = i >> 5;
            int q = i & 31;             // k = 4q
            int node = mBase + m;
            float4 v = make_float4(0.f, 0.f, 0.f, 0.f);
            if (node < N_NODES) {
                v = (h == 0) ? agg4[node * 32 + q] : x4[node * 32 + q];
            }
            __nv_bfloat16 h0 = __float2bfloat16_rn(v.x);
            __nv_bfloat16 h1 = __float2bfloat16_rn(v.y);
            __nv_bfloat16 h2 = __float2bfloat16_rn(v.z);
            __nv_bfloat16 h3 = __float2bfloat16_rn(v.w);
            __nv_bfloat16 l0 = __float2bfloat16_rn(v.x - __bfloat162float(h0));
            __nv_bfloat16 l1 = __float2bfloat16_rn(v.y - __bfloat162float(h1));
            __nv_bfloat16 l2 = __float2bfloat16_rn(v.z - __bfloat162float(h2));
            __nv_bfloat16 l3 = __float2bfloat16_rn(v.w - __bfloat162float(h3));
            uint32_t hp0 = (uint32_t)__bfloat16_as_ushort(h0) | ((uint32_t)__bfloat16_as_ushort(h1) << 16);
            uint32_t hp1 = (uint32_t)__bfloat16_as_ushort(h2) | ((uint32_t)__bfloat16_as_ushort(h3) << 16);
            uint32_t lp0 = (uint32_t)__bfloat16_as_ushort(l0) | ((uint32_t)__bfloat16_as_ushort(l1) << 16);
            uint32_t lp1 = (uint32_t)__bfloat16_as_ushort(l2) | ((uint32_t)__bfloat16_as_ushort(l3) << 16);
            uint32_t off = (uint32_t)m * PITCH_B + q * 8;
            *(uint32_t*)(sm + SM_AHI + off) = hp0;
            *(uint32_t*)(sm + SM_AHI + off + 4) = hp1;
            *(uint32_t*)(sm + SM_ALO + off) = lp0;
            *(uint32_t*)(sm + SM_ALO + off + 4) = lp1;
        }

        // ---- copy B half (hi+lo) into padded smem ----
#pragma unroll
        for (int p = 0; p < 16; p++) {
            int i = p * 256 + tid;      // 4096 over 2 images x 2048 uint4
            int img = i >> 11;
            int j = i & 2047;
            int r = j >> 4;
            int u = j & 15;
            const unsigned char* src = (img == 0 ? g_Bhi : g_Blo) + h * 32768 + r * 256 + u * 16;
            unsigned char* dst = (unsigned char*)sm + (img == 0 ? SM_BHI : SM_BLO) + r * PITCH_B + u * 16;
            *(uint4*)dst = *(const uint4*)src;
        }
        __syncthreads();

        // ---- MMA mainloop: 8 k-steps of 16 ----
        uint32_t aBaseHi = sb + SM_AHI + (warp_m * 32) * PITCH_B;
        uint32_t aBaseLo = sb + SM_ALO + (warp_m * 32) * PITCH_B;
        uint32_t bBaseHi = sb + SM_BHI + (warp_n * 64) * PITCH_B;
        uint32_t bBaseLo = sb + SM_BLO + (warp_n * 64) * PITCH_B;

#pragma unroll
        for (int ks = 0; ks < 8; ks++) {
            int kb = ks * 16;
            uint32_t ah[2][4], al[2][4];
#pragma unroll
            for (int mt = 0; mt < 2; mt++) {
                int row = mt * 16 + l8 + (sel & 1) * 8;
                int kk = kb + (sel >> 1) * 8;
                uint32_t o = (uint32_t)row * PITCH_B + kk * 2;
                ldsm4(ah[mt], aBaseHi + o);
                ldsm4(al[mt], aBaseLo + o);
            }
#pragma unroll
            for (int ntp = 0; ntp < 4; ntp++) {
                int row = ntp * 16 + (sel >> 1) * 8 + l8;
                int kk = kb + (sel & 1) * 8;
                uint32_t o = (uint32_t)row * PITCH_B + kk * 2;
                uint32_t bh[4], bl[4];
                ldsm4(bh, bBaseHi + o);
                ldsm4(bl, bBaseLo + o);
#pragma unroll
                for (int mt = 0; mt < 2; mt++) {
                    mma16816(acc[mt][ntp * 2],     ah[mt], bh[0], bh[1]);   // AhBh
                    mma16816(acc[mt][ntp * 2 + 1], ah[mt], bh[2], bh[3]);
                    mma16816(acc[mt][ntp * 2],     ah[mt], bl[0], bl[1]);   // AhBl
                    mma16816(acc[mt][ntp * 2 + 1], ah[mt], bl[2], bl[3]);
                    mma16816(acc[mt][ntp * 2],     al[mt], bh[0], bh[1]);   // AlBh
                    mma16816(acc[mt][ntp * 2 + 1], al[mt], bh[2], bh[3]);
                }
            }
        }
    }

    // ---- epilogue: relu + dot(W_out), smem atomic combine across warp cols ----
    __syncthreads();
#pragma unroll
    for (int mt = 0; mt < 2; mt++) {
        int r0 = warp_m * 32 + mt * 16 + (lane >> 2);
        float s0 = 0.f, s1 = 0.f;
#pragma unroll
        for (int nt = 0; nt < 8; nt++) {
            int c = warp_n * 64 + nt * 8 + 2 * (lane & 3);
            s0 += fmaxf(acc[mt][nt][0] + sB[c], 0.f) * sO[c];
            s0 += fmaxf(acc[mt][nt][1] + sB[c + 1], 0.f) * sO[c + 1];
            s1 += fmaxf(acc[mt][nt][2] + sB[c], 0.f) * sO[c];
            s1 += fmaxf(acc[mt][nt][3] + sB[c + 1], 0.f) * sO[c + 1];
        }
        atomicAdd(&sRes[r0], s0);
        atomicAdd(&sRes[r0 + 8], s1);
    }
    __syncthreads();
    if (tid < GEMM_TILE_M) {
        int node = mBase + tid;
        if (node < N_NODES) out[node] = sRes[tid] + bout[0];
    }
}

// ---------------- launch -----------------------------------------------------
extern "C" void kernel_launch(void* const* d_in, const int* in_sizes, int n_in,
                              void* d_out, int out_size) {
    const float* x      = (const float*)d_in[0];
    const int*   ei     = (const int*)d_in[1];
    const float* Wconv  = (const float*)d_in[2];
    const float* bconv  = (const float*)d_in[3];
    const float* Wproj  = (const float*)d_in[4];
    const float* bproj  = (const float*)d_in[5];
    const float* Wout   = (const float*)d_in[6];
    const float* bout   = (const float*)d_in[7];
    float* out = (float*)d_out;

    const int* rowv = ei;
    const int* colv = ei + N_EDGES;

    k_wconv<<<64, 256>>>(Wconv, Wproj);
    k_zero<<<(N_NODES + 255) / 256, 256>>>();
    k_count<<<(N_EDGES + 255) / 256, 256>>>(colv);
    k_prep<<<(N_NODES * 32 + 255) / 256, 256>>>(x);
    k_blocksum<<<NB, SCAN_BS>>>();
    k_scanbsum<<<1, 256>>>();
    k_scanblock<<<NB, SCAN_BS>>>();
    k_fill<<<(N_EDGES + 255) / 256, 256>>>(rowv, colv);

    long long agg_threads = (long long)N_NODES * 32;
    k_agg<<<(unsigned)((agg_threads + 255) / 256), 256>>>(x);

    static bool attr_set = false;
    if (!attr_set) {
        cudaFuncSetAttribute(k_gemm, cudaFuncAttributeMaxDynamicSharedMemorySize, SM_TOTAL);
        attr_set = true;
    }
    k_gemm<<<GEMM_GRID, 256, SM_TOTAL>>>(x, bconv, bproj, Wout, bout, out);
}

// round 6
// speedup vs baseline: 1.0085x; 1.0085x over previous
#include <cuda_runtime.h>
#include <cuda_bf16.h>
#include <cuda_fp16.h>
#include <cstdint>

#define N_NODES 100000
#define N_EDGES 1600000
#define D 128
#define SCAN_BS 512
#define NB ((N_NODES + SCAN_BS - 1) / SCAN_BS)   // 196
#define GEMM_TILE_M 128
#define GEMM_GRID ((N_NODES + GEMM_TILE_M - 1) / GEMM_TILE_M)   // 782
#define PITCH_B 272   // bytes per smem row: 128 bf16 = 256B + 16B pad (conflict-free ldmatrix)

// ---------------- scratch (__device__ globals; no allocation allowed) -------
__device__ float g_agg[N_NODES * D];     // dinv[c] * (sum dinv[r] x[r] + 2 dinv[c] x[c])
__device__ __half g_yh[N_NODES * D];     // fp16 prescaled dinv[r]*x[r]
__device__ float g_dinv[N_NODES];
__device__ int   g_cnt[N_NODES];
__device__ int   g_rank[N_EDGES];
__device__ int   g_rowptr[N_NODES];
__device__ int   g_src[N_EDGES];
__device__ int   g_bsum[NB];
__device__ int   g_bpre[NB];
// bf16 hi/lo weight images, layout [half][n:128][k:128] (B[n][k] = W[k_global][n])
__device__ __align__(16) unsigned char g_Bhi[65536];
__device__ __align__(16) unsigned char g_Blo[65536];

// ---------------- degree / CSR build ---------------------------------------
__global__ void k_zero() {
    int i = blockIdx.x * blockDim.x + threadIdx.x;
    if (i < N_NODES) g_cnt[i] = 0;
}

__global__ void k_count(const int* __restrict__ col) {
    int e = blockIdx.x * blockDim.x + threadIdx.x;
    if (e < N_EDGES) g_rank[e] = atomicAdd(&g_cnt[col[e]], 1);
}

__global__ void k_blocksum() {
    __shared__ int s[SCAN_BS];
    int t = threadIdx.x;
    int i = blockIdx.x * SCAN_BS + t;
    s[t] = (i < N_NODES) ? g_cnt[i] : 0;
    __syncthreads();
    for (int off = SCAN_BS / 2; off > 0; off >>= 1) {
        if (t < off) s[t] += s[t + off];
        __syncthreads();
    }
    if (t == 0) g_bsum[blockIdx.x] = s[0];
}

__global__ void k_scanbsum() {
    __shared__ int s[256];
    int t = threadIdx.x;
    int v = (t < NB) ? g_bsum[t] : 0;
    s[t] = v;
    __syncthreads();
    for (int off = 1; off < 256; off <<= 1) {
        int u = (t >= off) ? s[t - off] : 0;
        __syncthreads();
        s[t] += u;
        __syncthreads();
    }
    if (t < NB) g_bpre[t] = s[t] - v;
}

__global__ void k_scanblock() {
    __shared__ int s[SCAN_BS];
    int t = threadIdx.x;
    int i = blockIdx.x * SCAN_BS + t;
    int v = (i < N_NODES) ? g_cnt[i] : 0;
    s[t] = v;
    __syncthreads();
    for (int off = 1; off < SCAN_BS; off <<= 1) {
        int u = (t >= off) ? s[t - off] : 0;
        __syncthreads();
        s[t] += u;
        __syncthreads();
    }
    if (i < N_NODES) {
        g_rowptr[i] = s[t] - v + g_bpre[blockIdx.x];
        g_dinv[i] = rsqrtf((float)(v + 2));
    }
}

// y = dinv[node] * x, fp16 (needs dinv -> runs after k_scanblock)
__global__ void k_prep(const float* __restrict__ x) {
    int i = blockIdx.x * blockDim.x + threadIdx.x;   // float4 index, N*32
    if (i >= N_NODES * 32) return;
    int node = i >> 5;
    float dv = g_dinv[node];
    float4 v = ((const float4*)x)[i];
    __half2 a = __floats2half2_rn(dv * v.x, dv * v.y);
    __half2 b = __floats2half2_rn(dv * v.z, dv * v.w);
    uint2 u;
    u.x = *(uint32_t*)&a;
    u.y = *(uint32_t*)&b;
    ((uint2*)g_yh)[i] = u;
}

__global__ void k_fill(const int* __restrict__ rowv, const int* __restrict__ colv) {
    int e = blockIdx.x * blockDim.x + threadIdx.x;
    if (e >= N_EDGES) return;
    int pos = g_rowptr[colv[e]] + g_rank[e];
    g_src[pos] = rowv[e];
}

// ---------------- warp-per-node gather aggregation (prescaled fp16) ---------
__global__ void k_agg(const float* __restrict__ x) {
    int w = (blockIdx.x * blockDim.x + threadIdx.x) >> 5;
    int lane = threadIdx.x & 31;
    if (w >= N_NODES) return;
    const uint2* yh2 = (const uint2*)g_yh;   // 32 uint2 per row

    int start = g_rowptr[w];
    int cn = g_cnt[w];

    float ax = 0.f, ay = 0.f, az = 0.f, aw = 0.f;

    for (int base = 0; base < cn; base += 32) {
        int idx = 0;
        if (base + lane < cn) idx = g_src[start + base + lane];
        int m = min(32, cn - base);
        int j = 0;
        for (; j + 8 <= m; j += 8) {
            uint2 u[8];
#pragma unroll
            for (int q = 0; q < 8; q++) {
                int sv = __shfl_sync(0xffffffffu, idx, j + q);
                u[q] = yh2[sv * 32 + lane];
            }
#pragma unroll
            for (int q = 0; q < 8; q++) {
                float2 a = __half22float2(*(__half2*)&u[q].x);
                float2 b = __half22float2(*(__half2*)&u[q].y);
                ax += a.x; ay += a.y; az += b.x; aw += b.y;
            }
        }
        for (; j < m; j++) {
            int sv = __shfl_sync(0xffffffffu, idx, j);
            uint2 u0 = yh2[sv * 32 + lane];
            float2 a = __half22float2(*(__half2*)&u0.x);
            float2 b = __half22float2(*(__half2*)&u0.y);
            ax += a.x; ay += a.y; az += b.x; aw += b.y;
        }
    }

    // self-loop term in full fp32, then prescale everything by dinv[w]
    float dc = g_dinv[w];
    float4 xv = ((const float4*)x)[w * 32 + lane];
    float td = 2.f * dc;
    float4 r;
    r.x = dc * (ax + td * xv.x);
    r.y = dc * (ay + td * xv.y);
    r.z = dc * (az + td * xv.z);
    r.w = dc * (aw + td * xv.w);
    ((float4*)g_agg)[w * 32 + lane] = r;
}

// ---------------- weight pre-conversion (plain [half][n][k] layout) ---------
__global__ void k_wconv(const float* __restrict__ Wconv, const float* __restrict__ Wproj) {
    int t = blockIdx.x * blockDim.x + threadIdx.x;  // 16384 = 128 n * 128 k-pairs
    if (t >= 128 * 128) return;
    int n = t >> 7;
    int p = t & 127;
    int k0 = 2 * p, k1 = k0 + 1;
    float v0 = (k0 < D) ? Wconv[k0 * D + n] : Wproj[(k0 - D) * D + n];
    float v1 = (k1 < D) ? Wconv[k1 * D + n] : Wproj[(k1 - D) * D + n];
    __nv_bfloat16 h0 = __float2bfloat16_rn(v0);
    __nv_bfloat16 h1 = __float2bfloat16_rn(v1);
    __nv_bfloat16 l0 = __float2bfloat16_rn(v0 - __bfloat162float(h0));
    __nv_bfloat16 l1 = __float2bfloat16_rn(v1 - __bfloat162float(h1));
    uint32_t hp = (uint32_t)__bfloat16_as_ushort(h0) | ((uint32_t)__bfloat16_as_ushort(h1) << 16);
    uint32_t lp = (uint32_t)__bfloat16_as_ushort(l0) | ((uint32_t)__bfloat16_as_ushort(l1) << 16);
    int half = k0 >> 7;
    int klocal = k0 & 127;
    uint32_t off = ((uint32_t)half * 16384 + n * 128 + klocal) * 2;   // bytes
    *(uint32_t*)(g_Bhi + off) = hp;
    *(uint32_t*)(g_Blo + off) = lp;
}

// ---------------- mma.sync split-bf16 GEMM + fused epilogue -----------------
// smem byte offsets
#define SM_AHI 0
#define SM_ALO 34816
#define SM_BHI 69632
#define SM_BLO 104448
#define SM_MISC 139264
#define SM_TOTAL 140800

__device__ __forceinline__ uint32_t s2u(const void* p) {
    uint32_t a;
    asm("{ .reg .u64 t; cvta.to.shared.u64 t, %1; cvt.u32.u64 %0, t; }" : "=r"(a) : "l"(p));
    return a;
}
__device__ __forceinline__ void ldsm4(uint32_t* r, uint32_t addr) {
    asm volatile("ldmatrix.sync.aligned.m8n8.x4.shared.b16 {%0,%1,%2,%3}, [%4];"
                 : "=r"(r[0]), "=r"(r[1]), "=r"(r[2]), "=r"(r[3]) : "r"(addr));
}
__device__ __forceinline__ void mma16816(float* c, const uint32_t* a, uint32_t b0, uint32_t b1) {
    asm volatile(
        "mma.sync.aligned.m16n8k16.row.col.f32.bf16.bf16.f32 "
        "{%0,%1,%2,%3}, {%4,%5,%6,%7}, {%8,%9}, {%0,%1,%2,%3};"
        : "+f"(c[0]), "+f"(c[1]), "+f"(c[2]), "+f"(c[3])
        : "r"(a[0]), "r"(a[1]), "r"(a[2]), "r"(a[3]), "r"(b0), "r"(b1));
}

__global__ __launch_bounds__(256, 1)
void k_gemm(const float* __restrict__ x,
            const float* __restrict__ bconv, const float* __restrict__ bproj,
            const float* __restrict__ Wout,  const float* __restrict__ bout,
            float* __restrict__ out) {
    extern __shared__ char sm[];
    uint32_t sb = s2u(sm);
    int tid = threadIdx.x;
    int wid = tid >> 5;
    int lane = tid & 31;
    int mBase = blockIdx.x * GEMM_TILE_M;

    float* sB = (float*)(sm + SM_MISC);
    float* sO = (float*)(sm + SM_MISC + 512);
    float* sRes = (float*)(sm + SM_MISC + 1024);

    if (tid < D) {
        sB[tid] = bconv[tid] + bproj[tid];
        sO[tid] = Wout[tid];
        sRes[tid] = 0.f;
    }

    int warp_m = wid >> 1;
    int warp_n = wid & 1;

    float acc[2][8][4];
#pragma unroll
    for (int mt = 0; mt < 2; mt++)
#pragma unroll
        for (int nt = 0; nt < 8; nt++)
#pragma unroll
            for (int j = 0; j < 4; j++) acc[mt][nt][j] = 0.f;

    const float4* agg4 = (const float4*)g_agg;
    const float4* x4 = (const float4*)x;
    int l8 = lane & 7;
    int sel = lane >> 3;

    for (int h = 0; h < 2; h++) {
        __syncthreads();

        // ---- convert A half into smem hi/lo, padded rows ----
#pragma unroll
        for (int p = 0; p < 16; p++) {
            int i = p * 256 + tid;      // 4096 float4 over [128 rows][32 q]
            int m = i >> 5;
            int q = i & 31;
            int node = mBase + m;
            float4 v = make_float4(0.f, 0.f, 0.f, 0.f);
            if (node < N_NODES) {
                v = (h == 0) ? agg4[node * 32 + q] : x4[node * 32 + q];
            }
            __nv_bfloat16 h0 = __float2bfloat16_rn(v.x);
            __nv_bfloat16 h1 = __float2bfloat16_rn(v.y);
            __nv_bfloat16 h2 = __float2bfloat16_rn(v.z);
            __nv_bfloat16 h3 = __float2bfloat16_rn(v.w);
            __nv_bfloat16 l0 = __float2bfloat16_rn(v.x - __bfloat162float(h0));
            __nv_bfloat16 l1 = __float2bfloat16_rn(v.y - __bfloat162float(h1));
            __nv_bfloat16 l2 = __float2bfloat16_rn(v.z - __bfloat162float(h2));
            __nv_bfloat16 l3 = __float2bfloat16_rn(v.w - __bfloat162float(h3));
            uint32_t hp0 = (uint32_t)__bfloat16_as_ushort(h0) | ((uint32_t)__bfloat16_as_ushort(h1) << 16);
            uint32_t hp1 = (uint32_t)__bfloat16_as_ushort(h2) | ((uint32_t)__bfloat16_as_ushort(h3) << 16);
            uint32_t lp0 = (uint32_t)__bfloat16_as_ushort(l0) | ((uint32_t)__bfloat16_as_ushort(l1) << 16);
            uint32_t lp1 = (uint32_t)__bfloat16_as_ushort(l2) | ((uint32_t)__bfloat16_as_ushort(l3) << 16);
            uint32_t off = (uint32_t)m * PITCH_B + q * 8;
            *(uint32_t*)(sm + SM_AHI + off) = hp0;
            *(uint32_t*)(sm + SM_AHI + off + 4) = hp1;
            *(uint32_t*)(sm + SM_ALO + off) = lp0;
            *(uint32_t*)(sm + SM_ALO + off + 4) = lp1;
        }

        // ---- copy B half (hi+lo) into padded smem ----
#pragma unroll
        for (int p = 0; p < 16; p++) {
            int i = p * 256 + tid;
            int img = i >> 11;
            int j = i & 2047;
            int r = j >> 4;
            int u = j & 15;
            const unsigned char* src = (img == 0 ? g_Bhi : g_Blo) + h * 32768 + r * 256 + u * 16;
            unsigned char* dst = (unsigned char*)sm + (img == 0 ? SM_BHI : SM_BLO) + r * PITCH_B + u * 16;
            *(uint4*)dst = *(const uint4*)src;
        }
        __syncthreads();

        uint32_t aBaseHi = sb + SM_AHI + (warp_m * 32) * PITCH_B;
        uint32_t aBaseLo = sb + SM_ALO + (warp_m * 32) * PITCH_B;
        uint32_t bBaseHi = sb + SM_BHI + (warp_n * 64) * PITCH_B;
        uint32_t bBaseLo = sb + SM_BLO + (warp_n * 64) * PITCH_B;

#pragma unroll
        for (int ks = 0; ks < 8; ks++) {
            int kb = ks * 16;
            uint32_t ah[2][4], al[2][4];
#pragma unroll
            for (int mt = 0; mt < 2; mt++) {
                int row = mt * 16 + l8 + (sel & 1) * 8;
                int kk = kb + (sel >> 1) * 8;
                uint32_t o = (uint32_t)row * PITCH_B + kk * 2;
                ldsm4(ah[mt], aBaseHi + o);
                ldsm4(al[mt], aBaseLo + o);
            }
#pragma unroll
            for (int ntp = 0; ntp < 4; ntp++) {
                int row = ntp * 16 + (sel >> 1) * 8 + l8;
                int kk = kb + (sel & 1) * 8;
                uint32_t o = (uint32_t)row * PITCH_B + kk * 2;
                uint32_t bh[4], bl[4];
                ldsm4(bh, bBaseHi + o);
                ldsm4(bl, bBaseLo + o);
#pragma unroll
                for (int mt = 0; mt < 2; mt++) {
                    mma16816(acc[mt][ntp * 2],     ah[mt], bh[0], bh[1]);
                    mma16816(acc[mt][ntp * 2 + 1], ah[mt], bh[2], bh[3]);
                    mma16816(acc[mt][ntp * 2],     ah[mt], bl[0], bl[1]);
                    mma16816(acc[mt][ntp * 2 + 1], ah[mt], bl[2], bl[3]);
                    mma16816(acc[mt][ntp * 2],     al[mt], bh[0], bh[1]);
                    mma16816(acc[mt][ntp * 2 + 1], al[mt], bh[2], bh[3]);
                }
            }
        }
    }

    __syncthreads();
#pragma unroll
    for (int mt = 0; mt < 2; mt++) {
        int r0 = warp_m * 32 + mt * 16 + (lane >> 2);
        float s0 = 0.f, s1 = 0.f;
#pragma unroll
        for (int nt = 0; nt < 8; nt++) {
            int c = warp_n * 64 + nt * 8 + 2 * (lane & 3);
            s0 += fmaxf(acc[mt][nt][0] + sB[c], 0.f) * sO[c];
            s0 += fmaxf(acc[mt][nt][1] + sB[c + 1], 0.f) * sO[c + 1];
            s1 += fmaxf(acc[mt][nt][2] + sB[c], 0.f) * sO[c];
            s1 += fmaxf(acc[mt][nt][3] + sB[c + 1], 0.f) * sO[c + 1];
        }
        atomicAdd(&sRes[r0], s0);
        atomicAdd(&sRes[r0 + 8], s1);
    }
    __syncthreads();
    if (tid < GEMM_TILE_M) {
        int node = mBase + tid;
        if (node < N_NODES) out[node] = sRes[tid] + bout[0];
    }
}

// ---------------- launch -----------------------------------------------------
extern "C" void kernel_launch(void* const* d_in, const int* in_sizes, int n_in,
                              void* d_out, int out_size) {
    const float* x      = (const float*)d_in[0];
    const int*   ei     = (const int*)d_in[1];
    const float* Wconv  = (const float*)d_in[2];
    const float* bconv  = (const float*)d_in[3];
    const float* Wproj  = (const float*)d_in[4];
    const float* bproj  = (const float*)d_in[5];
    const float* Wout   = (const float*)d_in[6];
    const float* bout   = (const float*)d_in[7];
    float* out = (float*)d_out;

    const int* rowv = ei;
    const int* colv = ei + N_EDGES;

    k_wconv<<<64, 256>>>(Wconv, Wproj);
    k_zero<<<(N_NODES + 255) / 256, 256>>>();
    k_count<<<(N_EDGES + 255) / 256, 256>>>(colv);
    k_blocksum<<<NB, SCAN_BS>>>();
    k_scanbsum<<<1, 256>>>();
    k_scanblock<<<NB, SCAN_BS>>>();
    k_prep<<<(N_NODES * 32 + 255) / 256, 256>>>(x);
    k_fill<<<(N_EDGES + 255) / 256, 256>>>(rowv, colv);

    long long agg_threads = (long long)N_NODES * 32;
    k_agg<<<(unsigned)((agg_threads + 255) / 256), 256>>>(x);

    static bool attr_set = false;
    if (!attr_set) {
        cudaFuncSetAttribute(k_gemm, cudaFuncAttributeMaxDynamicSharedMemorySize, SM_TOTAL);
        attr_set = true;
    }
    k_gemm<<<GEMM_GRID, 256, SM_TOTAL>>>(x, bconv, bproj, Wout, bout, out);
}